// round 11
// baseline (speedup 1.0000x reference)
#include <cuda_runtime.h>
#include <cuda_bf16.h>

// DomainGate: T=8192 tokens, E=16 experts, capacity C = ceil(T/E) = 512.
// Output (flattened float32): [ l_aux(1), combine1_sec(T*E*C), dispatch_mask(T*E*C) ]
// combine[t, e, pos] = 1.0 where e = domain_ids[t], pos = # prior active
// same-expert tokens, iff token active (mask=0) and pos < C; all else 0.
// dispatch_mask identical. l_aux = 0.
//
// R8: fork the capture — scan (writes only g_slot) runs on a side stream
// CONCURRENTLY with the 536MB memset; `ones` joins both. Hides the ~7us scan.

#define NTOK 8192
#define NEXP 16
#define CAP  512
#define ROW  (NEXP * CAP)                    // 8192
#define COMBINE_ELEMS (NTOK * ROW)           // 67108864

#define SCAN_THREADS 512                     // 16 warps = 16 experts
#define TPT (NTOK / SCAN_THREADS)            // 16 tokens per thread

__device__ int g_slot[NTOK];                 // e*CAP+pos, or -1

// ---------------------------------------------------------------------------
// K_scan: ordered per-expert cumsum -> g_slot. Single block, 512 threads.
// ---------------------------------------------------------------------------
__global__ __launch_bounds__(SCAN_THREADS, 1)
void domain_gate_scan(const int* __restrict__ domain_ids,
                      const void* __restrict__ mask_raw) {
    __shared__ int cnt[SCAN_THREADS][NEXP + 1];   // +1 pad vs bank conflicts
    __shared__ int byte_mode;

    const int tid  = threadIdx.x;
    const int warp = tid >> 5;
    const int lane = tid & 31;
    const int base = tid * TPT;

    // ---- Mask layout detect (int32 vs bytes): one uint4 per thread covers the
    // first 8192 bytes exactly; int32 0/1 data has zero upper bytes everywhere.
    if (tid == 0) byte_mode = 0;
    __syncthreads();
    {
        const uint4 q = ((const uint4*)mask_raw)[tid];
        if ((q.x | q.y | q.z | q.w) & 0xFFFFFF00u) byte_mode = 1;
    }
    __syncthreads();
    const int bm = byte_mode;

    // ---- Phase 1: vector loads; pack 16 ids into 2 nibble words + 16 pad bits.
    unsigned int pk[2] = {0u, 0u};
    unsigned int pad   = 0u;
    const int4* ids4 = (const int4*)domain_ids;

    if (!bm) {
        const int4* m4 = (const int4*)mask_raw;
#pragma unroll
        for (int k = 0; k < 4; k++) {
            const int4 a = ids4[tid * 4 + k];
            const int4 m = m4[tid * 4 + k];
            const int i0 = k * 4;
            pk[i0 >> 3] |= (unsigned)(a.x & 15) << (((i0 + 0) & 7) * 4);
            pk[i0 >> 3] |= (unsigned)(a.y & 15) << (((i0 + 1) & 7) * 4);
            pk[i0 >> 3] |= (unsigned)(a.z & 15) << (((i0 + 2) & 7) * 4);
            pk[i0 >> 3] |= (unsigned)(a.w & 15) << (((i0 + 3) & 7) * 4);
            if (m.x) pad |= 1u << (i0 + 0);
            if (m.y) pad |= 1u << (i0 + 1);
            if (m.z) pad |= 1u << (i0 + 2);
            if (m.w) pad |= 1u << (i0 + 3);
        }
    } else {
        const unsigned char* mb = (const unsigned char*)mask_raw;
#pragma unroll
        for (int k = 0; k < 4; k++) {
            const int4 a = ids4[tid * 4 + k];
            const int i0 = k * 4;
            pk[i0 >> 3] |= (unsigned)(a.x & 15) << (((i0 + 0) & 7) * 4);
            pk[i0 >> 3] |= (unsigned)(a.y & 15) << (((i0 + 1) & 7) * 4);
            pk[i0 >> 3] |= (unsigned)(a.z & 15) << (((i0 + 2) & 7) * 4);
            pk[i0 >> 3] |= (unsigned)(a.w & 15) << (((i0 + 3) & 7) * 4);
            if (mb[base + i0 + 0]) pad |= 1u << (i0 + 0);
            if (mb[base + i0 + 1]) pad |= 1u << (i0 + 1);
            if (mb[base + i0 + 2]) pad |= 1u << (i0 + 2);
            if (mb[base + i0 + 3]) pad |= 1u << (i0 + 3);
        }
    }

    int local[NEXP];
#pragma unroll
    for (int e = 0; e < NEXP; e++) local[e] = 0;
#pragma unroll
    for (int i = 0; i < TPT; i++) {
        const int e = (pk[i >> 3] >> ((i & 7) * 4)) & 15;
        if (!((pad >> i) & 1u)) local[e]++;
    }
#pragma unroll
    for (int e = 0; e < NEXP; e++) cnt[tid][e] = local[e];
    __syncthreads();

    // ---- Phase 2: warp w scans expert w over 512 chunk counts.
    {
        const int e = warp;                    // 16 warps, 16 experts
        int carry = 0;
#pragma unroll
        for (int seg = 0; seg < 16; seg++) {
            const int i = seg * 32 + lane;
            const int v = cnt[i][e];
            int x = v;
#pragma unroll
            for (int d = 1; d < 32; d <<= 1) {
                const int y = __shfl_up_sync(0xFFFFFFFFu, x, d);
                if (lane >= d) x += y;
            }
            cnt[i][e] = carry + x - v;         // exclusive
            carry += __shfl_sync(0xFFFFFFFFu, x, 31);
        }
    }
    __syncthreads();

    // ---- Phase 3: replay, emit slot per token (int4 stores)
    int off[NEXP];
#pragma unroll
    for (int e = 0; e < NEXP; e++) off[e] = cnt[tid][e];

    int4* gs4 = (int4*)g_slot;
#pragma unroll
    for (int k = 0; k < 4; k++) {
        int4 sv;
        int* sp = (int*)&sv;
#pragma unroll
        for (int j = 0; j < 4; j++) {
            const int i = k * 4 + j;
            int s = -1;
            if (!((pad >> i) & 1u)) {
                const int e   = (pk[i >> 3] >> ((i & 7) * 4)) & 15;
                const int pos = off[e]++;
                if (pos < CAP) s = e * CAP + pos;
            }
            sp[j] = s;
        }
        gs4[tid * 4 + k] = sv;
    }
}

// ---------------------------------------------------------------------------
// K_ones: one thread per token; scattered 1.0 stores into both tensors.
// Wide grid keeps the ~29k scattered-store L1 wavefronts spread across SMs.
// ---------------------------------------------------------------------------
__global__ __launch_bounds__(256)
void domain_gate_ones(float* __restrict__ out) {
    const int t = blockIdx.x * 256 + threadIdx.x;   // 0..8191
    const int s = g_slot[t];
    if (s >= 0) {
        const size_t idx = 1 + (size_t)t * ROW + s;
        out[idx]                          = 1.0f;   // combine1_sec
        out[idx + (size_t)COMBINE_ELEMS]  = 1.0f;   // dispatch_mask
    }
}

extern "C" void kernel_launch(void* const* d_in, const int* in_sizes, int n_in,
                              void* d_out, int out_size) {
    // inputs: [0] input float32 [8192,1024] (unused),
    // [1] domain_ids int32 [8192], [2] mask [8192] (int32 or bytes; auto-detected)
    const int*  domain_ids = (const int*)d_in[1];
    const void* mask       = (const void*)d_in[2];
    float*      out        = (float*)d_out;

    // Fork the capture: scan runs on a side stream concurrently with the big
    // memset (scan writes only __device__ g_slot, no dependency on d_out).
    // No device memory is allocated: streams/events only.
    cudaStream_t side;
    cudaStreamCreateWithFlags(&side, cudaStreamNonBlocking);
    cudaEvent_t fork_ev, join_ev;
    cudaEventCreateWithFlags(&fork_ev, cudaEventDisableTiming);
    cudaEventCreateWithFlags(&join_ev, cudaEventDisableTiming);

    cudaEventRecord(fork_ev, 0);
    cudaStreamWaitEvent(side, fork_ev, 0);

    // Branch A (main stream): zero-fill 536MB at peak memset bandwidth.
    cudaMemsetAsync(d_out, 0, (size_t)out_size * sizeof(float), 0);

    // Branch B (side stream): ordered per-expert cumsum -> g_slot.
    domain_gate_scan<<<1, SCAN_THREADS, 0, side>>>(domain_ids, mask);
    cudaEventRecord(join_ev, side);

    // Join, then scatter the ~14.7k ones (depends on memset AND scan).
    cudaStreamWaitEvent(0, join_ev, 0);
    domain_gate_ones<<<NTOK / 256, 256>>>(out);
}

// round 12
// speedup vs baseline: 1.0052x; 1.0052x over previous
#include <cuda_runtime.h>
#include <cuda_bf16.h>

// DomainGate: T=8192 tokens, E=16 experts, capacity C = ceil(T/E) = 512.
// Output (flattened float32): [ l_aux(1), combine1_sec(T*E*C), dispatch_mask(T*E*C) ]
// combine[t, e, pos] = 1.0 where e = domain_ids[t], pos = # prior active
// same-expert tokens, iff token active (mask=0) and pos < C; all else 0.
// dispatch_mask identical. l_aux = 0.
//
// R11: best measured pieces combined — R7's warp-parallel scan (~5us) feeding
// R6's fused zero+one row-fill (77.4us, same write ceiling as memset but the
// ones ride along free). Drops the separate memset node AND the ones kernel.

#define NTOK 8192
#define NEXP 16
#define CAP  512
#define ROW  (NEXP * CAP)                    // 8192 floats per row
#define COMBINE_ELEMS (NTOK * ROW)           // 67108864

#define SCAN_THREADS 512                     // 16 warps = 16 experts
#define TPT (NTOK / SCAN_THREADS)            // 16 tokens per thread

__device__ int g_slot[NTOK];                 // e*CAP+pos, or -1

// ---------------------------------------------------------------------------
// K_scan: ordered per-expert cumsum -> g_slot. Single block, 512 threads.
// ---------------------------------------------------------------------------
__global__ __launch_bounds__(SCAN_THREADS, 1)
void domain_gate_scan(const int* __restrict__ domain_ids,
                      const void* __restrict__ mask_raw) {
    __shared__ int cnt[SCAN_THREADS][NEXP + 1];   // +1 pad vs bank conflicts
    __shared__ int byte_mode;

    const int tid  = threadIdx.x;
    const int warp = tid >> 5;
    const int lane = tid & 31;
    const int base = tid * TPT;

    // ---- Mask layout detect (int32 vs bytes): one uint4 per thread covers the
    // first 8192 bytes; int32 0/1 data has zero upper bytes everywhere.
    if (tid == 0) byte_mode = 0;
    __syncthreads();
    {
        const uint4 q = ((const uint4*)mask_raw)[tid];
        if ((q.x | q.y | q.z | q.w) & 0xFFFFFF00u) byte_mode = 1;
    }
    __syncthreads();
    const int bm = byte_mode;

    // ---- Phase 1: vector loads; pack 16 ids into 2 nibble words + 16 pad bits.
    unsigned int pk[2] = {0u, 0u};
    unsigned int pad   = 0u;
    const int4* ids4 = (const int4*)domain_ids;

    if (!bm) {
        const int4* m4 = (const int4*)mask_raw;
#pragma unroll
        for (int k = 0; k < 4; k++) {
            const int4 a = ids4[tid * 4 + k];
            const int4 m = m4[tid * 4 + k];
            const int i0 = k * 4;
            pk[i0 >> 3] |= (unsigned)(a.x & 15) << (((i0 + 0) & 7) * 4);
            pk[i0 >> 3] |= (unsigned)(a.y & 15) << (((i0 + 1) & 7) * 4);
            pk[i0 >> 3] |= (unsigned)(a.z & 15) << (((i0 + 2) & 7) * 4);
            pk[i0 >> 3] |= (unsigned)(a.w & 15) << (((i0 + 3) & 7) * 4);
            if (m.x) pad |= 1u << (i0 + 0);
            if (m.y) pad |= 1u << (i0 + 1);
            if (m.z) pad |= 1u << (i0 + 2);
            if (m.w) pad |= 1u << (i0 + 3);
        }
    } else {
        const unsigned char* mb = (const unsigned char*)mask_raw;
#pragma unroll
        for (int k = 0; k < 4; k++) {
            const int4 a = ids4[tid * 4 + k];
            const int i0 = k * 4;
            pk[i0 >> 3] |= (unsigned)(a.x & 15) << (((i0 + 0) & 7) * 4);
            pk[i0 >> 3] |= (unsigned)(a.y & 15) << (((i0 + 1) & 7) * 4);
            pk[i0 >> 3] |= (unsigned)(a.z & 15) << (((i0 + 2) & 7) * 4);
            pk[i0 >> 3] |= (unsigned)(a.w & 15) << (((i0 + 3) & 7) * 4);
            if (mb[base + i0 + 0]) pad |= 1u << (i0 + 0);
            if (mb[base + i0 + 1]) pad |= 1u << (i0 + 1);
            if (mb[base + i0 + 2]) pad |= 1u << (i0 + 2);
            if (mb[base + i0 + 3]) pad |= 1u << (i0 + 3);
        }
    }

    int local[NEXP];
#pragma unroll
    for (int e = 0; e < NEXP; e++) local[e] = 0;
#pragma unroll
    for (int i = 0; i < TPT; i++) {
        const int e = (pk[i >> 3] >> ((i & 7) * 4)) & 15;
        if (!((pad >> i) & 1u)) local[e]++;
    }
#pragma unroll
    for (int e = 0; e < NEXP; e++) cnt[tid][e] = local[e];
    __syncthreads();

    // ---- Phase 2: warp w scans expert w over 512 chunk counts (shuffle scan).
    {
        const int e = warp;
        int carry = 0;
#pragma unroll
        for (int seg = 0; seg < 16; seg++) {
            const int i = seg * 32 + lane;
            const int v = cnt[i][e];
            int x = v;
#pragma unroll
            for (int d = 1; d < 32; d <<= 1) {
                const int y = __shfl_up_sync(0xFFFFFFFFu, x, d);
                if (lane >= d) x += y;
            }
            cnt[i][e] = carry + x - v;         // exclusive
            carry += __shfl_sync(0xFFFFFFFFu, x, 31);
        }
    }
    __syncthreads();

    // ---- Phase 3: replay, emit slot per token (int4 stores)
    int off[NEXP];
#pragma unroll
    for (int e = 0; e < NEXP; e++) off[e] = cnt[tid][e];

    int4* gs4 = (int4*)g_slot;
#pragma unroll
    for (int k = 0; k < 4; k++) {
        int4 sv;
        int* sp = (int*)&sv;
#pragma unroll
        for (int j = 0; j < 4; j++) {
            const int i = k * 4 + j;
            int s = -1;
            if (!((pad >> i) & 1u)) {
                const int e   = (pk[i >> 3] >> ((i & 7) * 4)) & 15;
                const int pos = off[e]++;
                if (pos < CAP) s = e * CAP + pos;
            }
            sp[j] = s;
        }
        gs4[tid * 4 + k] = sv;
    }
}

// ---------------------------------------------------------------------------
// K_fill: one CTA per token t. Writes combine row t AND dmask row t (64KB),
// with the single 1.0 fused into the store values via compare-select.
// This hits the same chip write ceiling as cudaMemset but subsumes the ones.
// ---------------------------------------------------------------------------
#define FILL_THREADS 256

__global__ __launch_bounds__(FILL_THREADS, 8)
void domain_gate_fill(float* __restrict__ out) {
    const int t   = blockIdx.x;              // 0..8191
    const int tid = threadIdx.x;

    const int s = g_slot[t];                 // broadcast across block via L1

    float* __restrict__ pc = out + 1 + (size_t)t * ROW;    // combine row
    float* __restrict__ pd = pc + (size_t)COMBINE_ELEMS;   // dmask row

    if (t == 0 && tid == 0) out[0] = 0.0f;   // l_aux

    // Rows start 4B past 16B alignment: scalar head (0..2) and tail (8191),
    // float4 body over [3, 8191) = 2047 vectors (16B-aligned).
    if (tid < 3) {
        const float v = (tid == s) ? 1.0f : 0.0f;
        pc[tid] = v;
        pd[tid] = v;
    }
    if (tid == 3) {
        const float v = (s == ROW - 1) ? 1.0f : 0.0f;
        pc[ROW - 1] = v;
        pd[ROW - 1] = v;
    }

    float4* __restrict__ vc = (float4*)(pc + 3);
    float4* __restrict__ vd = (float4*)(pd + 3);
#pragma unroll
    for (int k = 0; k < 8; k++) {
        const int idx = tid + k * FILL_THREADS;   // 0..2047
        if (idx < 2047) {
            const int e0 = 3 + idx * 4;           // row-local element of .x
            float4 v;
            v.x = (e0 + 0 == s) ? 1.0f : 0.0f;
            v.y = (e0 + 1 == s) ? 1.0f : 0.0f;
            v.z = (e0 + 2 == s) ? 1.0f : 0.0f;
            v.w = (e0 + 3 == s) ? 1.0f : 0.0f;
            vc[idx] = v;
            vd[idx] = v;
        }
    }
}

extern "C" void kernel_launch(void* const* d_in, const int* in_sizes, int n_in,
                              void* d_out, int out_size) {
    // inputs: [0] input float32 [8192,1024] (unused),
    // [1] domain_ids int32 [8192], [2] mask [8192] (int32 or bytes; auto-detected)
    const int*  domain_ids = (const int*)d_in[1];
    const void* mask       = (const void*)d_in[2];
    float*      out        = (float*)d_out;

    domain_gate_scan<<<1, SCAN_THREADS>>>(domain_ids, mask);
    domain_gate_fill<<<NTOK, FILL_THREADS>>>(out);
}

// round 13
// speedup vs baseline: 1.0982x; 1.0925x over previous
#include <cuda_runtime.h>
#include <cuda_bf16.h>

// DomainGate: T=8192 tokens, E=16 experts, capacity C = ceil(T/E) = 512.
// Output (flattened float32): [ l_aux(1), combine1_sec(T*E*C), dispatch_mask(T*E*C) ]
// combine[t, e, pos] = 1.0 where e = domain_ids[t], pos = # prior active
// same-expert tokens, iff token active (mask=0) and pos < C; all else 0.
// dispatch_mask identical. l_aux = 0.
//
// R12: the 12us single-CTA scan is replaced by a parallel rank formulation:
//  K_ballot (32 CTAs): per-expert active-token bitmasks via __ballot_sync.
//  K_fill: each row-CTA computes pos(t) = popcount-prefix of its expert's
//  bitmask inline (L2-cached 16KB, hidden under the 64KB row stores).

#define NTOK 8192
#define NEXP 16
#define CAP  512
#define ROW  (NEXP * CAP)                    // 8192 floats per row
#define COMBINE_ELEMS (NTOK * ROW)           // 67108864
#define NGROUP (NTOK / 32)                   // 256 bitmask words per expert

__device__ unsigned int g_bm[NEXP * NGROUP]; // bit j of [e*256+w]: token 32w+j active & expert e
__device__ int          g_eid[NTOK];         // expert id, or -1 if padded

// ---------------------------------------------------------------------------
// K_ballot: 32 CTAs x 256 threads, one warp per 32-token group.
// ---------------------------------------------------------------------------
__global__ __launch_bounds__(256)
void domain_gate_ballot(const int* __restrict__ domain_ids,
                        const void* __restrict__ mask_raw) {
    __shared__ int byte_mode;

    const int tid  = threadIdx.x;
    const int t    = blockIdx.x * 256 + tid;   // 0..8191
    const int lane = tid & 31;
    const int wgrp = t >> 5;                   // bitmask word index

    // Mask layout detect (int32 vs bytes), per block over the first 8192 bytes
    // (valid address range in both layouts; int32 0/1 has zero upper bytes).
    if (tid == 0) byte_mode = 0;
    __syncthreads();
    {
        const uint4* m16 = (const uint4*)mask_raw;
        const uint4 a = m16[tid];
        const uint4 b = m16[tid + 256];
        if ((a.x | a.y | a.z | a.w | b.x | b.y | b.z | b.w) & 0xFFFFFF00u)
            byte_mode = 1;
    }
    __syncthreads();

    const int e = domain_ids[t] & 15;
    int padv;
    if (byte_mode) padv = ((const unsigned char*)mask_raw)[t];
    else           padv = ((const int*)mask_raw)[t];
    const bool active = (padv == 0);

    // 16 ballots: lane e2 keeps the ballot for expert e2
    unsigned int my = 0u;
#pragma unroll
    for (int e2 = 0; e2 < NEXP; e2++) {
        const unsigned int b = __ballot_sync(0xFFFFFFFFu, active && (e == e2));
        if (lane == e2) my = b;
    }
    if (lane < NEXP) g_bm[lane * NGROUP + wgrp] = my;

    g_eid[t] = active ? e : -1;
}

// ---------------------------------------------------------------------------
// K_fill: one CTA per token t. Computes pos(t) from the expert bitmask, then
// writes combine row t AND dmask row t (64KB) with the 1.0 fused in.
// ---------------------------------------------------------------------------
#define FILL_THREADS 256

__global__ __launch_bounds__(FILL_THREADS, 8)
void domain_gate_fill(float* __restrict__ out) {
    __shared__ int sh_part[8];
    __shared__ int sh_e;

    const int t   = blockIdx.x;              // 0..8191
    const int tid = threadIdx.x;

    if (tid == 0) sh_e = g_eid[t];
    __syncthreads();
    const int se = sh_e;

    // pos = # active same-expert tokens before t (popcount prefix of bitmask)
    if (se >= 0) {
        const int W = t >> 5, R = t & 31;
        int v = 0;
        if (tid < W)       v = __popc(g_bm[se * NGROUP + tid]);
        else if (tid == W) v = __popc(g_bm[se * NGROUP + W] &
                                      (R ? ((1u << R) - 1u) : 0u));
        v = __reduce_add_sync(0xFFFFFFFFu, v);
        if ((tid & 31) == 0) sh_part[tid >> 5] = v;
    }
    __syncthreads();

    int s = -1;
    if (se >= 0) {
        const int pos = sh_part[0] + sh_part[1] + sh_part[2] + sh_part[3] +
                        sh_part[4] + sh_part[5] + sh_part[6] + sh_part[7];
        if (pos < CAP) s = se * CAP + pos;   // capacity drop -> stays -1
    }

    float* __restrict__ pc = out + 1 + (size_t)t * ROW;    // combine row
    float* __restrict__ pd = pc + (size_t)COMBINE_ELEMS;   // dmask row

    if (t == 0 && tid == 0) out[0] = 0.0f;   // l_aux

    // Rows start 4B past 16B alignment: scalar head (0..2) and tail (8191),
    // float4 body over [3, 8191) = 2047 vectors (16B-aligned).
    if (tid < 3) {
        const float v = (tid == s) ? 1.0f : 0.0f;
        pc[tid] = v;
        pd[tid] = v;
    }
    if (tid == 3) {
        const float v = (s == ROW - 1) ? 1.0f : 0.0f;
        pc[ROW - 1] = v;
        pd[ROW - 1] = v;
    }

    float4* __restrict__ vc = (float4*)(pc + 3);
    float4* __restrict__ vd = (float4*)(pd + 3);
#pragma unroll
    for (int k = 0; k < 8; k++) {
        const int idx = tid + k * FILL_THREADS;   // 0..2047
        if (idx < 2047) {
            const int e0 = 3 + idx * 4;           // row-local element of .x
            float4 v;
            v.x = (e0 + 0 == s) ? 1.0f : 0.0f;
            v.y = (e0 + 1 == s) ? 1.0f : 0.0f;
            v.z = (e0 + 2 == s) ? 1.0f : 0.0f;
            v.w = (e0 + 3 == s) ? 1.0f : 0.0f;
            vc[idx] = v;
            vd[idx] = v;
        }
    }
}

extern "C" void kernel_launch(void* const* d_in, const int* in_sizes, int n_in,
                              void* d_out, int out_size) {
    // inputs: [0] input float32 [8192,1024] (unused),
    // [1] domain_ids int32 [8192], [2] mask [8192] (int32 or bytes; auto-detected)
    const int*  domain_ids = (const int*)d_in[1];
    const void* mask       = (const void*)d_in[2];
    float*      out        = (float*)d_out;

    domain_gate_ballot<<<NTOK / 256, 256>>>(domain_ids, mask);
    domain_gate_fill<<<NTOK, FILL_THREADS>>>(out);
}